// round 10
// baseline (speedup 1.0000x reference)
#include <cuda_runtime.h>
#include <cuda_bf16.h>

// Problem constants
#define BB 4
#define PP 64
#define SS 8
#define YD 16
#define GD 48
#define NOUT (BB*PP*PP*SS*SS)          // 1,048,576 outputs
#define NTAB (BB*PP*SS)                // 2048 entries in c1/c2 tables

// Precomputed per-(b,p,s) linear terms (bias folded into c1)
__device__ float g_c1[NTAB];
__device__ float g_c2[NTAB];

__device__ __forceinline__ float dot4(float4 v, float4 w) {
    return fmaf(v.x, w.x, fmaf(v.y, w.y, fmaf(v.z, w.z, v.w * w.w)));
}

// ---------------------------------------------------------------------------
// Prep: c1[b,p,s] = y[b,p,s,:]·Wy[0:16] + bg + by,  c2 = y·Wy[16:32]
// Fires launch_dependents as soon as tables are globally visible, so the
// main grid (waiting at its top) starts with minimal gap.
// ---------------------------------------------------------------------------
__global__ void prep_kernel(const float* __restrict__ y,
                            const float* __restrict__ Wy,
                            const float* __restrict__ by,
                            const float* __restrict__ bg) {
    int idx = blockIdx.x * blockDim.x + threadIdx.x;
    if (idx < NTAB) {
        const float4* yr = (const float4*)(y + (size_t)idx * YD);
        const float4* w1 = (const float4*)Wy;
        const float4* w2 = (const float4*)(Wy + YD);
        float4 y0 = yr[0], y1 = yr[1], y2 = yr[2], y3 = yr[3];
        float a = dot4(y0, w1[0]) + dot4(y1, w1[1])
                + dot4(y2, w1[2]) + dot4(y3, w1[3]);
        float b = dot4(y0, w2[0]) + dot4(y1, w2[1])
                + dot4(y2, w2[2]) + dot4(y3, w2[3]);
        g_c1[idx] = a + by[0] + bg[0];
        g_c2[idx] = b;
    }
    __threadfence();
    asm volatile("griddepcontrol.launch_dependents;" ::: "memory");
}

// ---------------------------------------------------------------------------
// Main — byte-identical to the proven R2 kernel (32 regs, 90% occ, 33.0us)
// except for one griddepcontrol.wait as the VERY FIRST statement (nothing
// live before it -> register allocation of the body is untouched).
//   - each warp = 32 consecutive outputs = one 6KB contiguous tile of g
//   - 2 batches x 6 coalesced LDG.128 (lane l -> float4 f = l + 32k)
//   - weight column f%12 = (l%12+8k)%12 cycles {A,B,C}: 3 register float4s
//   - per-lane partial -> smem (conflict-free STS.32)
//   - lane r sums its 12 partials via 3 conflict-free LDS.128
//   - + table terms from g_c1/g_c2
// ---------------------------------------------------------------------------
#define WARPS_PER_BLOCK 8

__global__ __launch_bounds__(32 * WARPS_PER_BLOCK)
void main_kernel(const float* __restrict__ g,
                 const float* __restrict__ Wg,
                 float* __restrict__ out) {
    asm volatile("griddepcontrol.wait;" ::: "memory");

    __shared__ float part[WARPS_PER_BLOCK][12 * 32];

    const int lane = threadIdx.x & 31;
    const int wIn  = threadIdx.x >> 5;
    const int warp = blockIdx.x * WARPS_PER_BLOCK + wIn;
    const int base = warp * 32;

    // The 3 weight columns this lane ever needs (k%3 == 0,1,2 -> A,B,C)
    const int l12 = lane % 12;
    int cB = l12 + 8; if (cB >= 12) cB -= 12;
    int cC = l12 + 4; if (cC >= 12) cC -= 12;
    const float4* wv = (const float4*)Wg;
    const float4 wA = __ldg(wv + l12);
    const float4 wB = __ldg(wv + cB);
    const float4 wC = __ldg(wv + cC);

    const float4* gs = (const float4*)(g + (size_t)base * GD);
    float* p = part[wIn];

    // ---- batch 1: k = 0..5 (6 loads in flight) ----
    float4 v0 = __ldcs(gs + lane +   0);
    float4 v1 = __ldcs(gs + lane +  32);
    float4 v2 = __ldcs(gs + lane +  64);
    float4 v3 = __ldcs(gs + lane +  96);
    float4 v4 = __ldcs(gs + lane + 128);
    float4 v5 = __ldcs(gs + lane + 160);
    p[lane +   0] = dot4(v0, wA);
    p[lane +  32] = dot4(v1, wB);
    p[lane +  64] = dot4(v2, wC);
    p[lane +  96] = dot4(v3, wA);
    p[lane + 128] = dot4(v4, wB);
    p[lane + 160] = dot4(v5, wC);

    // ---- batch 2: k = 6..11 ----
    float4 u0 = __ldcs(gs + lane + 192);
    float4 u1 = __ldcs(gs + lane + 224);
    float4 u2 = __ldcs(gs + lane + 256);
    float4 u3 = __ldcs(gs + lane + 288);
    float4 u4 = __ldcs(gs + lane + 320);
    float4 u5 = __ldcs(gs + lane + 352);
    p[lane + 192] = dot4(u0, wA);
    p[lane + 224] = dot4(u1, wB);
    p[lane + 256] = dot4(u2, wC);
    p[lane + 288] = dot4(u3, wA);
    p[lane + 320] = dot4(u4, wB);
    p[lane + 352] = dot4(u5, wC);

    __syncwarp();

    // ---- reduce: lane r owns output base+r, partials at p[12r .. 12r+11] ----
    const float4* pr = (const float4*)(p + lane * 12);   // 48B aligned
    float4 t0 = pr[0], t1 = pr[1], t2 = pr[2];
    float sum = ((t0.x + t0.y) + (t0.z + t0.w))
              + ((t1.x + t1.y) + (t1.z + t1.w))
              + ((t2.x + t2.y) + (t2.z + t2.w));

    // Broadcast terms: o = ((((b*P+i)*P+j)*S+si)*S+sj)
    const int o  = base + lane;
    const int sj = o & 7;
    const int si = (o >> 3) & 7;
    const int j  = (o >> 6) & 63;
    const int i  = (o >> 12) & 63;
    const int b  = o >> 18;
    sum += g_c1[(((b << 6) + j) << 3) + sj];   // ky1[b, j, sj] (+bias)
    sum += g_c2[(((b << 6) + i) << 3) + si];   // ky2[b, i, si]

    __stcs(out + o, sum);
}

// ---------------------------------------------------------------------------
// Launch: prep, then main with PDL; main's grid goes resident while prep
// runs and begins the instant prep signals.
// inputs (metadata order): y(32768), pairwise_g(50331648), Wy(32), by(1),
//                          Wg(48), bg(1)
// ---------------------------------------------------------------------------
extern "C" void kernel_launch(void* const* d_in, const int* in_sizes, int n_in,
                              void* d_out, int out_size) {
    const float* y  = (const float*)d_in[0];
    const float* g  = (const float*)d_in[1];
    const float* Wy = (const float*)d_in[2];
    const float* by = (const float*)d_in[3];
    const float* Wg = (const float*)d_in[4];
    const float* bg = (const float*)d_in[5];
    float* out = (float*)d_out;

    prep_kernel<<<(NTAB + 255) / 256, 256>>>(y, Wy, by, bg);

    cudaLaunchAttribute attrs[1];
    attrs[0].id = cudaLaunchAttributeProgrammaticStreamSerialization;
    attrs[0].val.programmaticStreamSerializationAllowed = 1;

    cudaLaunchConfig_t cfg = {};
    cfg.gridDim  = dim3(NOUT / 32 / WARPS_PER_BLOCK);   // 4096
    cfg.blockDim = dim3(32 * WARPS_PER_BLOCK);          // 256
    cfg.dynamicSmemBytes = 0;
    cfg.stream = 0;
    cfg.attrs = attrs;
    cfg.numAttrs = 1;

    cudaLaunchKernelEx(&cfg, main_kernel, g, Wg, out);
}

// round 11
// speedup vs baseline: 1.0580x; 1.0580x over previous
#include <cuda_runtime.h>
#include <cuda_bf16.h>

// Problem constants
#define BB 4
#define PP 64
#define SS 8
#define YD 16
#define GD 48
#define NOUT (BB*PP*PP*SS*SS)          // 1,048,576 outputs

#define WARPS_PER_BLOCK 8              // 256 threads = 256 consecutive outputs

__device__ __forceinline__ float dot4(float4 v, float4 w) {
    return fmaf(v.x, w.x, fmaf(v.y, w.y, fmaf(v.z, w.z, v.w * w.w)));
}

// ---------------------------------------------------------------------------
// Fused kernel. Block = 256 consecutive outputs: (b,i) fixed, j spans 4
// values, (si,sj) full.
//
// Lean prologue (low register peak): 160 threads each compute ONE dot4
// partial (entry e = tid>>2, quarter q = tid&3) into smem; 40 threads fold
// x4 into sc1[4][8] (= y[b,j0+jj,s,:]·Wy[0:16]+bias) and sc2[8]
// (= y[b,i,s,:]·Wy[16:32]). Two cheap barriers, ~8 live regs per thread.
//
// Hot loop (proven R2 schedule): per warp one 6KB g tile,
//   - 2 batches x 6 coalesced LDG.128 (lane l -> float4 f = l + 32k)
//   - weight column f%12 = (l%12+8k)%12 cycles {A,B,C}: 3 register float4s
//   - per-lane partial -> smem (conflict-free STS.32)
//   - lane r sums its 12 partials via 3 conflict-free LDS.128
//   - + sc1[jj][sj] + sc2[si] (broadcast LDS)
//
// __launch_bounds__(256, 7): cap at 36 regs = exactly 24 (6 float4 loads in
// flight) + 12 (3 weight float4s) — keeps the load batching intact (unlike
// the 32-reg cap of R6) while buying the 7th block/SM (56 warps, 87.5%).
// ---------------------------------------------------------------------------
__global__ __launch_bounds__(32 * WARPS_PER_BLOCK, 7)
void fused_kernel(const float* __restrict__ y,
                  const float* __restrict__ g,
                  const float* __restrict__ Wy,
                  const float* __restrict__ by,
                  const float* __restrict__ Wg,
                  const float* __restrict__ bg,
                  float* __restrict__ out) {
    __shared__ float part[WARPS_PER_BLOCK][12 * 32];
    __shared__ float pp[160];          // prologue dot4 partials
    __shared__ float sc1[4 * SS];      // c1[jj][s] (+bias)
    __shared__ float sc2[SS];          // c2[s]

    const int tid  = threadIdx.x;
    const int lane = tid & 31;
    const int wIn  = tid >> 5;
    const int blockBase = blockIdx.x * 256;

    // ---- lean prologue stage 1: 160 one-dot4 partials ----
    if (tid < 160) {
        const int e = tid >> 2;                      // table entry 0..39
        const int q = tid & 3;                       // quarter of the 16-dot
        const int b  =  blockBase >> 18;
        const int i  = (blockBase >> 12) & 63;
        const int j0 = (blockBase >> 6)  & 63;       // low 2 bits are 0
        int row, woff;
        if (e < 32) { row = ((b << 6) + j0 + (e >> 3)) * SS + (e & 7); woff = 0; }
        else        { row = ((b << 6) + i) * SS + (e - 32);            woff = YD; }
        float4 yv = __ldg((const float4*)(y + (size_t)row * YD) + q);
        float4 wv = __ldg((const float4*)(Wy + woff) + q);
        pp[tid] = dot4(yv, wv);
    }
    __syncthreads();
    // ---- stage 2: fold x4 into the tables ----
    if (tid < 40) {
        float d = (pp[4*tid] + pp[4*tid+1]) + (pp[4*tid+2] + pp[4*tid+3]);
        if (tid < 32) sc1[tid] = d + __ldg(by) + __ldg(bg);
        else          sc2[tid - 32] = d;
    }
    __syncthreads();

    // ---- per-lane weight columns: (lane%12 + {0,8,4}) % 12 ----
    const int l12 = lane % 12;
    int cB = l12 + 8; if (cB >= 12) cB -= 12;
    int cC = l12 + 4; if (cC >= 12) cC -= 12;
    const float4* wv = (const float4*)Wg;
    const float4 wA = __ldg(wv + l12);
    const float4 wB = __ldg(wv + cB);
    const float4 wC = __ldg(wv + cC);

    const int base = blockBase + wIn * 32;
    const float4* gs = (const float4*)(g + (size_t)base * GD);
    float* p = part[wIn];

    // ---- batch 1: k = 0..5 (6 loads in flight) ----
    float4 v0 = __ldcs(gs + lane +   0);
    float4 v1 = __ldcs(gs + lane +  32);
    float4 v2 = __ldcs(gs + lane +  64);
    float4 v3 = __ldcs(gs + lane +  96);
    float4 v4 = __ldcs(gs + lane + 128);
    float4 v5 = __ldcs(gs + lane + 160);
    p[lane +   0] = dot4(v0, wA);
    p[lane +  32] = dot4(v1, wB);
    p[lane +  64] = dot4(v2, wC);
    p[lane +  96] = dot4(v3, wA);
    p[lane + 128] = dot4(v4, wB);
    p[lane + 160] = dot4(v5, wC);

    // ---- batch 2: k = 6..11 ----
    float4 u0 = __ldcs(gs + lane + 192);
    float4 u1 = __ldcs(gs + lane + 224);
    float4 u2 = __ldcs(gs + lane + 256);
    float4 u3 = __ldcs(gs + lane + 288);
    float4 u4 = __ldcs(gs + lane + 320);
    float4 u5 = __ldcs(gs + lane + 352);
    p[lane + 192] = dot4(u0, wA);
    p[lane + 224] = dot4(u1, wB);
    p[lane + 256] = dot4(u2, wC);
    p[lane + 288] = dot4(u3, wA);
    p[lane + 320] = dot4(u4, wB);
    p[lane + 352] = dot4(u5, wC);

    __syncwarp();

    // ---- reduce: lane r owns output base+r, partials at p[12r .. 12r+11] ----
    const float4* pr = (const float4*)(p + lane * 12);   // 48B aligned
    float4 t0 = pr[0], t1 = pr[1], t2 = pr[2];
    float sum = ((t0.x + t0.y) + (t0.z + t0.w))
              + ((t1.x + t1.y) + (t1.z + t1.w))
              + ((t2.x + t2.y) + (t2.z + t2.w));

    // broadcast terms: warp's jj = wIn>>1, si0 = (wIn&1)*4
    sum += sc1[((wIn >> 1) << 3) + (lane & 7)];
    sum += sc2[((wIn & 1) << 2) + (lane >> 3)];

    __stcs(out + base + lane, sum);
}

// ---------------------------------------------------------------------------
// Launch
// inputs (metadata order): y(32768), pairwise_g(50331648), Wy(32), by(1),
//                          Wg(48), bg(1)
// ---------------------------------------------------------------------------
extern "C" void kernel_launch(void* const* d_in, const int* in_sizes, int n_in,
                              void* d_out, int out_size) {
    const float* y  = (const float*)d_in[0];
    const float* g  = (const float*)d_in[1];
    const float* Wy = (const float*)d_in[2];
    const float* by = (const float*)d_in[3];
    const float* Wg = (const float*)d_in[4];
    const float* bg = (const float*)d_in[5];
    float* out = (float*)d_out;

    const int blocks = NOUT / 256;                // 4096
    fused_kernel<<<blocks, 32 * WARPS_PER_BLOCK>>>(y, g, Wy, by, Wg, bg, out);
}